// round 15
// baseline (speedup 1.0000x reference)
#include <cuda_runtime.h>
#include <cuda_fp16.h>
#include <cuda_pipeline.h>
#include <mma.h>
using namespace nvcuda;

// Problem constants
#define CB 4
#define CS 2048
#define CD 1024
#define CH 16
#define CHD 64
#define CBH (CB*CH)

// Scratch (allocation-free)
__device__ __align__(16) __half g_qkv[(size_t)3*CBH*CS*CHD]; // [3][BH][S][HD]
__device__ __align__(16) __half g_y [(size_t)CB*CS*CD];      // [B][S][D]
__device__ __align__(16) __half g_xh[(size_t)CB*CS*CD];
__device__ __align__(16) __half g_wa[(size_t)CD*3*CD];
__device__ __align__(16) __half g_wp[(size_t)CD*CD];

// PDL: wait for the previous kernel in the stream (launch-attr gated).
__device__ __forceinline__ void gdc_wait() {
    asm volatile("griddepcontrol.wait;" ::: "memory");
}

// ---------------------------------------------------------------------------
// One fused fp32 -> fp16 conversion pass over x, Wa, Wp.
// ---------------------------------------------------------------------------
#define N4_X  (CB*CS*CD/4)
#define N4_WA (3*CD*CD/4)
#define N4_WP (CD*CD/4)

__global__ void cvt_all_kernel(const float* __restrict__ x,
                               const float* __restrict__ Wa,
                               const float* __restrict__ Wp,
                               __half* __restrict__ xh,
                               __half* __restrict__ wa,
                               __half* __restrict__ wp)
{
    const int i = blockIdx.x * blockDim.x + threadIdx.x;
    const float4* src;
    __half* dst;
    int j = i;
    if (i < N4_X)                      { src = (const float4*)x;  dst = xh; }
    else if (i < N4_X + N4_WA)         { src = (const float4*)Wa; dst = wa; j = i - N4_X; }
    else if (i < N4_X + N4_WA + N4_WP) { src = (const float4*)Wp; dst = wp; j = i - N4_X - N4_WA; }
    else return;
    float4 v = src[j];
    __half2 lo = __floats2half2_rn(v.x, v.y);
    __half2 hi = __floats2half2_rn(v.z, v.w);
    uint2 u;
    u.x = *(unsigned int*)&lo;
    u.y = *(unsigned int*)&hi;
    ((uint2*)dst)[j] = u;
}

// ---------------------------------------------------------------------------
// FP16 wmma GEMM, cp.async 4-stage, BK=32; warp-private epilogue staging.
// ---------------------------------------------------------------------------
#define BK 32
#define ALD 40
#define BLD 136
#define ST_HALFS (128*ALD + BK*BLD)
#define GEMM_SMEM (4*ST_HALFS*2)

template<int MODE>
__global__ void __launch_bounds__(256, 2) gemm_h(
    const __half* __restrict__ A, const __half* __restrict__ Bm,
    const float* __restrict__ bias, void* __restrict__ Cout,
    int M, int N, int K)
{
    extern __shared__ __half hsm[];
    const int tid = threadIdx.x;
    const int warp = tid >> 5, lane = tid & 31;
    const int wm = warp & 3, wn = warp >> 2;
    const int m0 = blockIdx.y * 128, n0 = blockIdx.x * 128;

    gdc_wait();   // PDL: inputs come from the previous kernel in-stream

    wmma::fragment<wmma::accumulator,16,16,16,float> cf[2][4];
    #pragma unroll
    for (int i = 0; i < 2; i++)
        #pragma unroll
        for (int j = 0; j < 4; j++) wmma::fill_fragment(cf[i][j], 0.f);

    auto issue = [&](int it) {
        __half* As = hsm + (it & 3) * ST_HALFS;
        __half* Bs = As + 128*ALD;
        const int k0 = it * BK;
        #pragma unroll
        for (int i = 0; i < 2; i++) {
            const int c = i * 256 + tid;
            const int row = c >> 2, kc = (c & 3) << 3;
            __pipeline_memcpy_async(&As[row * ALD + kc],
                &A[(size_t)(m0 + row) * K + k0 + kc], 16);
        }
        #pragma unroll
        for (int i = 0; i < 2; i++) {
            const int c = i * 256 + tid;
            const int row = c >> 4, nc = (c & 15) << 3;
            __pipeline_memcpy_async(&Bs[row * BLD + nc],
                &Bm[(size_t)(k0 + row) * N + n0 + nc], 16);
        }
        __pipeline_commit();
    };

    const int NT = K / BK;
    issue(0); issue(1);

    for (int it = 0; it < NT; it++) {
        if (it + 2 < NT)      { issue(it + 2); __pipeline_wait_prior(2); }
        else if (it + 1 < NT) { __pipeline_wait_prior(1); }
        else                  { __pipeline_wait_prior(0); }
        __syncthreads();

        const __half* As = hsm + (it & 3) * ST_HALFS;
        const __half* Bs = As + 128*ALD;
        #pragma unroll
        for (int kk = 0; kk < 2; kk++) {
            wmma::fragment<wmma::matrix_a,16,16,16,__half,wmma::row_major> af[2];
            #pragma unroll
            for (int i = 0; i < 2; i++)
                wmma::load_matrix_sync(af[i], &As[(wm*32 + i*16) * ALD + kk*16], ALD);
            #pragma unroll
            for (int j = 0; j < 4; j++) {
                wmma::fragment<wmma::matrix_b,16,16,16,__half,wmma::row_major> bf;
                wmma::load_matrix_sync(bf, &Bs[(kk*16) * BLD + wn*64 + j*16], BLD);
                #pragma unroll
                for (int i = 0; i < 2; i++)
                    wmma::mma_sync(cf[i][j], af[i], bf, cf[i][j]);
            }
        }
    }
    __syncthreads();   // all stage reads retired before smem reuse

    // Warp-private epilogue: stage 32x64 f32 into this warp's slab, syncwarp,
    // then each lane owns one full 64-col row (contiguous global segment).
    float* ws = (float*)hsm + warp * (32*68);
    #pragma unroll
    for (int i = 0; i < 2; i++)
        #pragma unroll
        for (int j = 0; j < 4; j++)
            wmma::store_matrix_sync(&ws[(i*16)*68 + j*16], cf[i][j], 68,
                                    wmma::mem_row_major);
    __syncwarp();

    const int m = m0 + wm*32 + lane;
    const int nb = n0 + wn*64;
    const float* wr = ws + lane*68;
    if (MODE == 0) {
        float* C = (float*)Cout + (size_t)m * N + nb;
        #pragma unroll
        for (int c = 0; c < 64; c += 4) {
            float4 v = *(const float4*)&wr[c];
            v.x += bias[nb + c];     v.y += bias[nb + c + 1];
            v.z += bias[nb + c + 2]; v.w += bias[nb + c + 3];
            *(float4*)&C[c] = v;
        }
    } else {
        // 64-col strip is exactly one head: single base address per lane.
        const int which = nb >> 10, d = nb & 1023;
        const int h = d >> 6;
        const int b = m >> 11, s = m & 2047;
        __half* C = (__half*)Cout +
            ((((size_t)which * CB + b) * CH + h) * CS + s) * CHD;
        #pragma unroll
        for (int c = 0; c < 64; c += 4) {
            float4 v = *(const float4*)&wr[c];
            __half2 p0 = __floats2half2_rn(v.x + bias[nb + c],
                                           v.y + bias[nb + c + 1]);
            __half2 p1 = __floats2half2_rn(v.z + bias[nb + c + 2],
                                           v.w + bias[nb + c + 3]);
            uint2 u; u.x = *(unsigned*)&p0; u.y = *(unsigned*)&p1;
            *(uint2*)&C[c] = u;
        }
    }
}

// ---------------------------------------------------------------------------
// Raw-mma helpers
// ---------------------------------------------------------------------------
__device__ __forceinline__ void ldsm4(unsigned* d, unsigned a) {
    asm volatile("ldmatrix.sync.aligned.m8n8.x4.shared.b16 {%0,%1,%2,%3}, [%4];"
        : "=r"(d[0]), "=r"(d[1]), "=r"(d[2]), "=r"(d[3]) : "r"(a));
}
__device__ __forceinline__ void ldsm4t(unsigned* d, unsigned a) {
    asm volatile("ldmatrix.sync.aligned.m8n8.x4.trans.shared.b16 {%0,%1,%2,%3}, [%4];"
        : "=r"(d[0]), "=r"(d[1]), "=r"(d[2]), "=r"(d[3]) : "r"(a));
}
__device__ __forceinline__ void mma16816(float* c, const unsigned* a,
                                         unsigned b0, unsigned b1) {
    asm volatile(
        "mma.sync.aligned.m16n8k16.row.col.f32.f16.f16.f32 "
        "{%0,%1,%2,%3}, {%4,%5,%6,%7}, {%8,%9}, {%0,%1,%2,%3};"
        : "+f"(c[0]), "+f"(c[1]), "+f"(c[2]), "+f"(c[3])
        : "r"(a[0]), "r"(a[1]), "r"(a[2]), "r"(a[3]), "r"(b0), "r"(b1));
}
__device__ __forceinline__ void mma16816h(unsigned* c, const unsigned* a,
                                          unsigned b0, unsigned b1) {
    asm volatile(
        "mma.sync.aligned.m16n8k16.row.col.f16.f16.f16.f16 "
        "{%0,%1}, {%2,%3,%4,%5}, {%6,%7}, {%0,%1};"
        : "+r"(c[0]), "+r"(c[1])
        : "r"(a[0]), "r"(a[1]), "r"(a[2]), "r"(a[3]), "r"(b0), "r"(b1));
}
__device__ __forceinline__ unsigned hex2(unsigned x) {   // 2^x on packed half2
    unsigned d;
    asm("ex2.approx.f16x2 %0, %1;" : "=r"(d) : "r"(x));
    return d;
}

// ---------------------------------------------------------------------------
// Flash attention (R13, proven): raw mma, 128 q/CTA, 128-key super-tiles,
// fp16-acc QK^T (acc == P fragment layout), ex2.f16x2 softmax, ALU rowsums,
// causal, single-pass.
// ---------------------------------------------------------------------------
#define HLD 72
#define KVT2 (128*HLD)
#define QTH (128*HLD)
#define ATTN_SMEM ((QTH + 4*KVT2) * 2)   // 92160 B

__global__ void __launch_bounds__(256, 2) attn_tc(
    const __half* __restrict__ qkv, __half* __restrict__ y)
{
    extern __shared__ __half smh[];
    __half* Qs = smh;
    __half* KV = smh + QTH;

    const int bh = blockIdx.y;
    const int qt = gridDim.x - 1 - blockIdx.x;
    const int t  = threadIdx.x;
    const int warp = t >> 5, lane = t & 31;
    const int rb = warp;
    const int g = lane >> 2, tg = lane & 3;

    gdc_wait();   // PDL: qkv comes from the QKV GEMM

    const size_t hsz = (size_t)CS * CHD;
    const __half* Qg = qkv + (size_t)bh * hsz + (size_t)qt * 128 * 64;
    const __half* Kg = qkv + ((size_t)CBH + bh) * hsz;
    const __half* Vg = qkv + ((size_t)2*CBH + bh) * hsz;

    auto issueKV = [&](int st) {
        __half* Kd = KV + (st & 1) * 2 * KVT2;
        __half* Vd = Kd + KVT2;
        const __half* Ksrc = Kg + (size_t)st * 128 * 64;
        const __half* Vsrc = Vg + (size_t)st * 128 * 64;
        #pragma unroll
        for (int i = 0; i < 4; i++) {
            const int c = i * 256 + t;
            const int row = c >> 3, c8 = (c & 7) << 3;
            __pipeline_memcpy_async(&Kd[row*HLD + c8], &Ksrc[row*64 + c8], 16);
            __pipeline_memcpy_async(&Vd[row*HLD + c8], &Vsrc[row*64 + c8], 16);
        }
        __pipeline_commit();
    };

    const int nkt = qt + 1;

    #pragma unroll
    for (int i = 0; i < 4; i++) {
        const int c = i * 256 + t;
        const int row = c >> 3, c8 = (c & 7) << 3;
        __pipeline_memcpy_async(&Qs[row*HLD + c8], &Qg[row*64 + c8], 16);
    }
    issueKV(0);

    __pipeline_wait_prior(0);
    __syncthreads();

    unsigned qf[4][4];
    {
        const unsigned qb = (unsigned)__cvta_generic_to_shared(Qs);
        const int qrow = rb*16 + (lane & 15);
        const int qcoff = (lane >> 4) * 8;
        const __half2 qscale = __float2half2_rn(0.18033688f);  // log2(e)/8
        #pragma unroll
        for (int kc = 0; kc < 4; kc++) {
            ldsm4(qf[kc], qb + (unsigned)(qrow*HLD + kc*16 + qcoff) * 2u);
            #pragma unroll
            for (int j = 0; j < 4; j++) {
                __half2 v = *(__half2*)&qf[kc][j];
                v = __hmul2(v, qscale);
                qf[kc][j] = *(unsigned*)&v;
            }
        }
    }

    float yacc[8][4];
    #pragma unroll
    for (int i = 0; i < 8; i++)
        #pragma unroll
        for (int j = 0; j < 4; j++) yacc[i][j] = 0.f;
    float rs0 = 0.f, rs1 = 0.f;

    const unsigned kvb = (unsigned)__cvta_generic_to_shared(KV);
    const int krow  = ((lane >> 4) << 3) + (lane & 7);
    const int kcoff = ((lane >> 3) & 1) * 8;
    const int row0  = rb*16 + g;
    const int qabs0 = qt*128 + row0;

    for (int st = 0; st < nkt; st++) {
        if (st > 0) {
            __pipeline_wait_prior(0);
            __syncthreads();
        }
        if (st + 1 < nkt) issueKV(st + 1);

        const unsigned KsB = kvb + (unsigned)((st & 1) * 2 * KVT2) * 2u;
        const unsigned VsB = KsB + (unsigned)KVT2 * 2u;
        const bool diag = (st == nkt - 1);

        #pragma unroll
        for (int sub = 0; sub < 2; sub++) {
            if (diag && sub == 1 && rb < 4) break;

            const unsigned Kb32 = KsB + (unsigned)(sub * 64 * HLD) * 2u;
            const unsigned Vb32 = VsB + (unsigned)(sub * 64 * HLD) * 2u;

            unsigned sacc[8][2];
            #pragma unroll
            for (int i = 0; i < 8; i++) { sacc[i][0] = 0u; sacc[i][1] = 0u; }

            #pragma unroll
            for (int kc = 0; kc < 4; kc++) {
                const unsigned cb = (unsigned)(kc*16 + kcoff) * 2u;
                #pragma unroll
                for (int kb = 0; kb < 4; kb++) {
                    unsigned kf[4];
                    ldsm4(kf, Kb32 + (unsigned)((krow + kb*16)*HLD)*2u + cb);
                    mma16816h(sacc[kb*2],     qf[kc], kf[0], kf[1]);
                    mma16816h(sacc[kb*2 + 1], qf[kc], kf[2], kf[3]);
                }
            }

            if (diag) {
                const int kbase = st*128 + sub*64;
                #pragma unroll
                for (int nb = 0; nb < 8; nb++) {
                    const int cb = kbase + nb*8 + 2*tg;
                    __half2 m0 = __floats2half2_rn(cb > qabs0     ? -30000.f : 0.f,
                                                   cb + 1 > qabs0 ? -30000.f : 0.f);
                    __half2 m1 = __floats2half2_rn(cb > qabs0 + 8     ? -30000.f : 0.f,
                                                   cb + 1 > qabs0 + 8 ? -30000.f : 0.f);
                    __half2 v0 = __hadd2(*(__half2*)&sacc[nb][0], m0);
                    __half2 v1 = __hadd2(*(__half2*)&sacc[nb][1], m1);
                    sacc[nb][0] = *(unsigned*)&v0;
                    sacc[nb][1] = *(unsigned*)&v1;
                }
            }

            unsigned pf[4][4];
            #pragma unroll
            for (int c = 0; c < 4; c++) {
                pf[c][0] = hex2(sacc[2*c][0]);
                pf[c][1] = hex2(sacc[2*c][1]);
                pf[c][2] = hex2(sacc[2*c + 1][0]);
                pf[c][3] = hex2(sacc[2*c + 1][1]);
            }

            {
                __half2 a0 = __hadd2(__hadd2(*(__half2*)&pf[0][0], *(__half2*)&pf[0][2]),
                                     __hadd2(*(__half2*)&pf[1][0], *(__half2*)&pf[1][2]));
                __half2 a1 = __hadd2(__hadd2(*(__half2*)&pf[2][0], *(__half2*)&pf[2][2]),
                                     __hadd2(*(__half2*)&pf[3][0], *(__half2*)&pf[3][2]));
                __half2 s0 = __hadd2(a0, a1);
                rs0 += __low2float(s0) + __high2float(s0);

                __half2 b0 = __hadd2(__hadd2(*(__half2*)&pf[0][1], *(__half2*)&pf[0][3]),
                                     __hadd2(*(__half2*)&pf[1][1], *(__half2*)&pf[1][3]));
                __half2 b1 = __hadd2(__hadd2(*(__half2*)&pf[2][1], *(__half2*)&pf[2][3]),
                                     __hadd2(*(__half2*)&pf[3][1], *(__half2*)&pf[3][3]));
                __half2 s1 = __hadd2(b0, b1);
                rs1 += __low2float(s1) + __high2float(s1);
            }

            #pragma unroll
            for (int nd = 0; nd < 8; nd++) {
                unsigned vfA[4], vfB[4];
                ldsm4t(vfA, Vb32 + (unsigned)( lane      *HLD + nd*8) * 2u);
                ldsm4t(vfB, Vb32 + (unsigned)((lane + 32)*HLD + nd*8) * 2u);
                mma16816(yacc[nd], pf[0], vfA[0], vfA[1]);
                mma16816(yacc[nd], pf[1], vfA[2], vfA[3]);
                mma16816(yacc[nd], pf[2], vfB[0], vfB[1]);
                mma16816(yacc[nd], pf[3], vfB[2], vfB[3]);
            }
        }
    }

    rs0 += __shfl_xor_sync(0xffffffffu, rs0, 1);
    rs0 += __shfl_xor_sync(0xffffffffu, rs0, 2);
    rs1 += __shfl_xor_sync(0xffffffffu, rs1, 1);
    rs1 += __shfl_xor_sync(0xffffffffu, rs1, 2);
    const float inv0 = 1.f / rs0;
    const float inv1 = 1.f / rs1;

    const int b = bh >> 4, h = bh & 15;
    const int q0 = qt*128 + row0;
    __half* yo0 = y + ((size_t)(b * CS + q0)) * CD + h*64;
    __half* yo1 = yo0 + (size_t)8 * CD;
    #pragma unroll
    for (int nd = 0; nd < 8; nd++) {
        const int col = nd*8 + 2*tg;
        __half2 h0 = __floats2half2_rn(yacc[nd][0]*inv0, yacc[nd][1]*inv0);
        __half2 h1 = __floats2half2_rn(yacc[nd][2]*inv1, yacc[nd][3]*inv1);
        *(__half2*)&yo0[col] = h0;
        *(__half2*)&yo1[col] = h1;
    }
}

// ---------------------------------------------------------------------------
extern "C" void kernel_launch(void* const* d_in, const int* in_sizes, int n_in,
                              void* d_out, int out_size)
{
    const float* x  = (const float*)d_in[0];
    const float* Wa = (const float*)d_in[1];
    const float* ba = (const float*)d_in[2];
    const float* Wp = (const float*)d_in[3];
    const float* bp = (const float*)d_in[4];
    float* out = (float*)d_out;

    __half *qkv, *y, *xh, *wa, *wp;
    cudaGetSymbolAddress((void**)&qkv, g_qkv);
    cudaGetSymbolAddress((void**)&y,   g_y);
    cudaGetSymbolAddress((void**)&xh,  g_xh);
    cudaGetSymbolAddress((void**)&wa,  g_wa);
    cudaGetSymbolAddress((void**)&wp,  g_wp);

    cudaFuncSetAttribute(gemm_h<0>,
        cudaFuncAttributeMaxDynamicSharedMemorySize, GEMM_SMEM);
    cudaFuncSetAttribute(gemm_h<1>,
        cudaFuncAttributeMaxDynamicSharedMemorySize, GEMM_SMEM);
    cudaFuncSetAttribute(attn_tc,
        cudaFuncAttributeMaxDynamicSharedMemorySize, ATTN_SMEM);

    const int ncv = N4_X + N4_WA + N4_WP;
    cvt_all_kernel<<<(ncv + 255)/256, 256>>>(x, Wa, Wp, xh, wa, wp);

    // PDL launches: each may begin launching while the predecessor drains;
    // consumers gate on griddepcontrol.wait at kernel entry.
    cudaLaunchAttribute at[1];
    at[0].id = cudaLaunchAttributeProgrammaticStreamSerialization;
    at[0].val.programmaticStreamSerializationAllowed = 1;

    cudaLaunchConfig_t cfg = {};
    cfg.blockDim = dim3(256, 1, 1);
    cfg.attrs = at;
    cfg.numAttrs = 1;
    cfg.stream = 0;

    // QKV: [8192,1024] @ [1024,3072] -> fp16 scatter [3][BH][S][HD]
    cfg.gridDim = dim3(3*CD/128, CB*CS/128, 1);
    cfg.dynamicSmemBytes = GEMM_SMEM;
    cudaLaunchKernelEx(&cfg, gemm_h<1>,
        (const __half*)xh, (const __half*)wa, ba, (void*)qkv,
        CB*CS, 3*CD, CD);

    // Attention
    cfg.gridDim = dim3(CS/128, CBH, 1);
    cfg.dynamicSmemBytes = ATTN_SMEM;
    cudaLaunchKernelEx(&cfg, attn_tc, (const __half*)qkv, y);

    // Proj: [8192,1024] @ [1024,1024] -> fp32 out
    cfg.gridDim = dim3(CD/128, CB*CS/128, 1);
    cfg.dynamicSmemBytes = GEMM_SMEM;
    cudaLaunchKernelEx(&cfg, gemm_h<0>,
        (const __half*)y, (const __half*)wp, bp, (void*)out,
        CB*CS, CD, CD);
}

// round 16
// speedup vs baseline: 1.0858x; 1.0858x over previous
#include <cuda_runtime.h>
#include <cuda_fp16.h>
#include <cuda_pipeline.h>
#include <mma.h>
using namespace nvcuda;

// Problem constants
#define CB 4
#define CS 2048
#define CD 1024
#define CH 16
#define CHD 64
#define CBH (CB*CH)

// Scratch (allocation-free)
__device__ __align__(16) __half g_qkv[(size_t)3*CBH*CS*CHD]; // [3][BH][S][HD]
__device__ __align__(16) __half g_y [(size_t)CB*CS*CD];      // [B][S][D]
__device__ __align__(16) __half g_xh[(size_t)CB*CS*CD];
__device__ __align__(16) __half g_wa[(size_t)CD*3*CD];
__device__ __align__(16) __half g_wp[(size_t)CD*CD];

// ---------------------------------------------------------------------------
// One fused fp32 -> fp16 conversion pass over x, Wa, Wp.
// ---------------------------------------------------------------------------
#define N4_X  (CB*CS*CD/4)
#define N4_WA (3*CD*CD/4)
#define N4_WP (CD*CD/4)

__global__ void cvt_all_kernel(const float* __restrict__ x,
                               const float* __restrict__ Wa,
                               const float* __restrict__ Wp,
                               __half* __restrict__ xh,
                               __half* __restrict__ wa,
                               __half* __restrict__ wp)
{
    const int i = blockIdx.x * blockDim.x + threadIdx.x;
    const float4* src;
    __half* dst;
    int j = i;
    if (i < N4_X)                      { src = (const float4*)x;  dst = xh; }
    else if (i < N4_X + N4_WA)         { src = (const float4*)Wa; dst = wa; j = i - N4_X; }
    else if (i < N4_X + N4_WA + N4_WP) { src = (const float4*)Wp; dst = wp; j = i - N4_X - N4_WA; }
    else return;
    float4 v = src[j];
    __half2 lo = __floats2half2_rn(v.x, v.y);
    __half2 hi = __floats2half2_rn(v.z, v.w);
    uint2 u;
    u.x = *(unsigned int*)&lo;
    u.y = *(unsigned int*)&hi;
    ((uint2*)dst)[j] = u;
}

// ---------------------------------------------------------------------------
// FP16 wmma GEMM, cp.async 4-stage, BK=32. Warp-private epilogue slab with
// ROW-PARALLEL lane mapping (coalesced 256B/128B row segments).
// ---------------------------------------------------------------------------
#define BK 32
#define ALD 40
#define BLD 136
#define ST_HALFS (128*ALD + BK*BLD)
#define GEMM_SMEM (4*ST_HALFS*2)

template<int MODE>
__global__ void __launch_bounds__(256, 2) gemm_h(
    const __half* __restrict__ A, const __half* __restrict__ Bm,
    const float* __restrict__ bias, void* __restrict__ Cout,
    int M, int N, int K)
{
    extern __shared__ __half hsm[];
    const int tid = threadIdx.x;
    const int warp = tid >> 5, lane = tid & 31;
    const int wm = warp & 3, wn = warp >> 2;
    const int m0 = blockIdx.y * 128, n0 = blockIdx.x * 128;

    wmma::fragment<wmma::accumulator,16,16,16,float> cf[2][4];
    #pragma unroll
    for (int i = 0; i < 2; i++)
        #pragma unroll
        for (int j = 0; j < 4; j++) wmma::fill_fragment(cf[i][j], 0.f);

    auto issue = [&](int it) {
        __half* As = hsm + (it & 3) * ST_HALFS;
        __half* Bs = As + 128*ALD;
        const int k0 = it * BK;
        #pragma unroll
        for (int i = 0; i < 2; i++) {
            const int c = i * 256 + tid;
            const int row = c >> 2, kc = (c & 3) << 3;
            __pipeline_memcpy_async(&As[row * ALD + kc],
                &A[(size_t)(m0 + row) * K + k0 + kc], 16);
        }
        #pragma unroll
        for (int i = 0; i < 2; i++) {
            const int c = i * 256 + tid;
            const int row = c >> 4, nc = (c & 15) << 3;
            __pipeline_memcpy_async(&Bs[row * BLD + nc],
                &Bm[(size_t)(k0 + row) * N + n0 + nc], 16);
        }
        __pipeline_commit();
    };

    const int NT = K / BK;
    issue(0); issue(1);

    for (int it = 0; it < NT; it++) {
        if (it + 2 < NT)      { issue(it + 2); __pipeline_wait_prior(2); }
        else if (it + 1 < NT) { __pipeline_wait_prior(1); }
        else                  { __pipeline_wait_prior(0); }
        __syncthreads();

        const __half* As = hsm + (it & 3) * ST_HALFS;
        const __half* Bs = As + 128*ALD;
        #pragma unroll
        for (int kk = 0; kk < 2; kk++) {
            wmma::fragment<wmma::matrix_a,16,16,16,__half,wmma::row_major> af[2];
            #pragma unroll
            for (int i = 0; i < 2; i++)
                wmma::load_matrix_sync(af[i], &As[(wm*32 + i*16) * ALD + kk*16], ALD);
            #pragma unroll
            for (int j = 0; j < 4; j++) {
                wmma::fragment<wmma::matrix_b,16,16,16,__half,wmma::row_major> bf;
                wmma::load_matrix_sync(bf, &Bs[(kk*16) * BLD + wn*64 + j*16], BLD);
                #pragma unroll
                for (int i = 0; i < 2; i++)
                    wmma::mma_sync(cf[i][j], af[i], bf, cf[i][j]);
            }
        }
    }
    __syncthreads();   // retire stage-buffer reads before smem reuse

    // Warp-private slab; then ROW-parallel output: for each row, lanes write
    // consecutive column pairs (fully coalesced), bias hoisted per lane.
    float* ws = (float*)hsm + warp * (32*68);
    #pragma unroll
    for (int i = 0; i < 2; i++)
        #pragma unroll
        for (int j = 0; j < 4; j++)
            wmma::store_matrix_sync(&ws[(i*16)*68 + j*16], cf[i][j], 68,
                                    wmma::mem_row_major);
    __syncwarp();

    const int nb = n0 + wn*64;
    const int c2 = 2*lane;
    const float b0v = bias[nb + c2], b1v = bias[nb + c2 + 1];
    const int mbase = m0 + wm*32;
    if (MODE == 0) {
        float* C = (float*)Cout + (size_t)mbase * N + nb + c2;
        #pragma unroll
        for (int r = 0; r < 32; r++) {
            float2 v = *(float2*)&ws[r*68 + c2];
            v.x += b0v; v.y += b1v;
            *(float2*)&C[(size_t)r * N] = v;
        }
    } else {
        // 64-col strip = exactly one head; 32-row strip never crosses a batch.
        const int which = nb >> 10, d = nb & 1023;
        const int h = d >> 6;
        const int b = mbase >> 11, s = mbase & 2047;
        __half* C = (__half*)Cout +
            ((((size_t)which * CB + b) * CH + h) * CS + s) * CHD + c2;
        #pragma unroll
        for (int r = 0; r < 32; r++) {
            float2 v = *(float2*)&ws[r*68 + c2];
            __half2 p = __floats2half2_rn(v.x + b0v, v.y + b1v);
            *(__half2*)&C[(size_t)r * CHD] = p;
        }
    }
}

// ---------------------------------------------------------------------------
// Raw-mma helpers
// ---------------------------------------------------------------------------
__device__ __forceinline__ void ldsm4(unsigned* d, unsigned a) {
    asm volatile("ldmatrix.sync.aligned.m8n8.x4.shared.b16 {%0,%1,%2,%3}, [%4];"
        : "=r"(d[0]), "=r"(d[1]), "=r"(d[2]), "=r"(d[3]) : "r"(a));
}
__device__ __forceinline__ void ldsm4t(unsigned* d, unsigned a) {
    asm volatile("ldmatrix.sync.aligned.m8n8.x4.trans.shared.b16 {%0,%1,%2,%3}, [%4];"
        : "=r"(d[0]), "=r"(d[1]), "=r"(d[2]), "=r"(d[3]) : "r"(a));
}
__device__ __forceinline__ void mma16816(float* c, const unsigned* a,
                                         unsigned b0, unsigned b1) {
    asm volatile(
        "mma.sync.aligned.m16n8k16.row.col.f32.f16.f16.f32 "
        "{%0,%1,%2,%3}, {%4,%5,%6,%7}, {%8,%9}, {%0,%1,%2,%3};"
        : "+f"(c[0]), "+f"(c[1]), "+f"(c[2]), "+f"(c[3])
        : "r"(a[0]), "r"(a[1]), "r"(a[2]), "r"(a[3]), "r"(b0), "r"(b1));
}
__device__ __forceinline__ void mma16816h(unsigned* c, const unsigned* a,
                                          unsigned b0, unsigned b1) {
    asm volatile(
        "mma.sync.aligned.m16n8k16.row.col.f16.f16.f16.f16 "
        "{%0,%1}, {%2,%3,%4,%5}, {%6,%7}, {%0,%1};"
        : "+r"(c[0]), "+r"(c[1])
        : "r"(a[0]), "r"(a[1]), "r"(a[2]), "r"(a[3]), "r"(b0), "r"(b1));
}
__device__ __forceinline__ unsigned hex2(unsigned x) {   // 2^x on packed half2
    unsigned d;
    asm("ex2.approx.f16x2 %0, %1;" : "=r"(d) : "r"(x));
    return d;
}

// ---------------------------------------------------------------------------
// Flash attention (R13, proven): raw mma, 128 q/CTA, 128-key super-tiles,
// fp16-acc QK^T (acc == P fragment layout), ex2.f16x2 softmax, ALU rowsums,
// causal, single-pass.
// ---------------------------------------------------------------------------
#define HLD 72
#define KVT2 (128*HLD)
#define QTH (128*HLD)
#define ATTN_SMEM ((QTH + 4*KVT2) * 2)   // 92160 B

__global__ void __launch_bounds__(256, 2) attn_tc(
    const __half* __restrict__ qkv, __half* __restrict__ y)
{
    extern __shared__ __half smh[];
    __half* Qs = smh;
    __half* KV = smh + QTH;

    const int bh = blockIdx.y;
    const int qt = gridDim.x - 1 - blockIdx.x;
    const int t  = threadIdx.x;
    const int warp = t >> 5, lane = t & 31;
    const int rb = warp;
    const int g = lane >> 2, tg = lane & 3;

    const size_t hsz = (size_t)CS * CHD;
    const __half* Qg = qkv + (size_t)bh * hsz + (size_t)qt * 128 * 64;
    const __half* Kg = qkv + ((size_t)CBH + bh) * hsz;
    const __half* Vg = qkv + ((size_t)2*CBH + bh) * hsz;

    auto issueKV = [&](int st) {
        __half* Kd = KV + (st & 1) * 2 * KVT2;
        __half* Vd = Kd + KVT2;
        const __half* Ksrc = Kg + (size_t)st * 128 * 64;
        const __half* Vsrc = Vg + (size_t)st * 128 * 64;
        #pragma unroll
        for (int i = 0; i < 4; i++) {
            const int c = i * 256 + t;
            const int row = c >> 3, c8 = (c & 7) << 3;
            __pipeline_memcpy_async(&Kd[row*HLD + c8], &Ksrc[row*64 + c8], 16);
            __pipeline_memcpy_async(&Vd[row*HLD + c8], &Vsrc[row*64 + c8], 16);
        }
        __pipeline_commit();
    };

    const int nkt = qt + 1;

    #pragma unroll
    for (int i = 0; i < 4; i++) {
        const int c = i * 256 + t;
        const int row = c >> 3, c8 = (c & 7) << 3;
        __pipeline_memcpy_async(&Qs[row*HLD + c8], &Qg[row*64 + c8], 16);
    }
    issueKV(0);

    __pipeline_wait_prior(0);
    __syncthreads();

    unsigned qf[4][4];
    {
        const unsigned qb = (unsigned)__cvta_generic_to_shared(Qs);
        const int qrow = rb*16 + (lane & 15);
        const int qcoff = (lane >> 4) * 8;
        const __half2 qscale = __float2half2_rn(0.18033688f);  // log2(e)/8
        #pragma unroll
        for (int kc = 0; kc < 4; kc++) {
            ldsm4(qf[kc], qb + (unsigned)(qrow*HLD + kc*16 + qcoff) * 2u);
            #pragma unroll
            for (int j = 0; j < 4; j++) {
                __half2 v = *(__half2*)&qf[kc][j];
                v = __hmul2(v, qscale);
                qf[kc][j] = *(unsigned*)&v;
            }
        }
    }

    float yacc[8][4];
    #pragma unroll
    for (int i = 0; i < 8; i++)
        #pragma unroll
        for (int j = 0; j < 4; j++) yacc[i][j] = 0.f;
    float rs0 = 0.f, rs1 = 0.f;

    const unsigned kvb = (unsigned)__cvta_generic_to_shared(KV);
    const int krow  = ((lane >> 4) << 3) + (lane & 7);
    const int kcoff = ((lane >> 3) & 1) * 8;
    const int row0  = rb*16 + g;
    const int qabs0 = qt*128 + row0;

    for (int st = 0; st < nkt; st++) {
        if (st > 0) {
            __pipeline_wait_prior(0);
            __syncthreads();
        }
        if (st + 1 < nkt) issueKV(st + 1);

        const unsigned KsB = kvb + (unsigned)((st & 1) * 2 * KVT2) * 2u;
        const unsigned VsB = KsB + (unsigned)KVT2 * 2u;
        const bool diag = (st == nkt - 1);

        #pragma unroll
        for (int sub = 0; sub < 2; sub++) {
            if (diag && sub == 1 && rb < 4) break;

            const unsigned Kb32 = KsB + (unsigned)(sub * 64 * HLD) * 2u;
            const unsigned Vb32 = VsB + (unsigned)(sub * 64 * HLD) * 2u;

            unsigned sacc[8][2];
            #pragma unroll
            for (int i = 0; i < 8; i++) { sacc[i][0] = 0u; sacc[i][1] = 0u; }

            #pragma unroll
            for (int kc = 0; kc < 4; kc++) {
                const unsigned cb = (unsigned)(kc*16 + kcoff) * 2u;
                #pragma unroll
                for (int kb = 0; kb < 4; kb++) {
                    unsigned kf[4];
                    ldsm4(kf, Kb32 + (unsigned)((krow + kb*16)*HLD)*2u + cb);
                    mma16816h(sacc[kb*2],     qf[kc], kf[0], kf[1]);
                    mma16816h(sacc[kb*2 + 1], qf[kc], kf[2], kf[3]);
                }
            }

            if (diag) {
                const int kbase = st*128 + sub*64;
                #pragma unroll
                for (int nb = 0; nb < 8; nb++) {
                    const int cb = kbase + nb*8 + 2*tg;
                    __half2 m0 = __floats2half2_rn(cb > qabs0     ? -30000.f : 0.f,
                                                   cb + 1 > qabs0 ? -30000.f : 0.f);
                    __half2 m1 = __floats2half2_rn(cb > qabs0 + 8     ? -30000.f : 0.f,
                                                   cb + 1 > qabs0 + 8 ? -30000.f : 0.f);
                    __half2 v0 = __hadd2(*(__half2*)&sacc[nb][0], m0);
                    __half2 v1 = __hadd2(*(__half2*)&sacc[nb][1], m1);
                    sacc[nb][0] = *(unsigned*)&v0;
                    sacc[nb][1] = *(unsigned*)&v1;
                }
            }

            unsigned pf[4][4];
            #pragma unroll
            for (int c = 0; c < 4; c++) {
                pf[c][0] = hex2(sacc[2*c][0]);
                pf[c][1] = hex2(sacc[2*c][1]);
                pf[c][2] = hex2(sacc[2*c + 1][0]);
                pf[c][3] = hex2(sacc[2*c + 1][1]);
            }

            {
                __half2 a0 = __hadd2(__hadd2(*(__half2*)&pf[0][0], *(__half2*)&pf[0][2]),
                                     __hadd2(*(__half2*)&pf[1][0], *(__half2*)&pf[1][2]));
                __half2 a1 = __hadd2(__hadd2(*(__half2*)&pf[2][0], *(__half2*)&pf[2][2]),
                                     __hadd2(*(__half2*)&pf[3][0], *(__half2*)&pf[3][2]));
                __half2 s0 = __hadd2(a0, a1);
                rs0 += __low2float(s0) + __high2float(s0);

                __half2 b0 = __hadd2(__hadd2(*(__half2*)&pf[0][1], *(__half2*)&pf[0][3]),
                                     __hadd2(*(__half2*)&pf[1][1], *(__half2*)&pf[1][3]));
                __half2 b1 = __hadd2(__hadd2(*(__half2*)&pf[2][1], *(__half2*)&pf[2][3]),
                                     __hadd2(*(__half2*)&pf[3][1], *(__half2*)&pf[3][3]));
                __half2 s1 = __hadd2(b0, b1);
                rs1 += __low2float(s1) + __high2float(s1);
            }

            #pragma unroll
            for (int nd = 0; nd < 8; nd++) {
                unsigned vfA[4], vfB[4];
                ldsm4t(vfA, Vb32 + (unsigned)( lane      *HLD + nd*8) * 2u);
                ldsm4t(vfB, Vb32 + (unsigned)((lane + 32)*HLD + nd*8) * 2u);
                mma16816(yacc[nd], pf[0], vfA[0], vfA[1]);
                mma16816(yacc[nd], pf[1], vfA[2], vfA[3]);
                mma16816(yacc[nd], pf[2], vfB[0], vfB[1]);
                mma16816(yacc[nd], pf[3], vfB[2], vfB[3]);
            }
        }
    }

    rs0 += __shfl_xor_sync(0xffffffffu, rs0, 1);
    rs0 += __shfl_xor_sync(0xffffffffu, rs0, 2);
    rs1 += __shfl_xor_sync(0xffffffffu, rs1, 1);
    rs1 += __shfl_xor_sync(0xffffffffu, rs1, 2);
    const float inv0 = 1.f / rs0;
    const float inv1 = 1.f / rs1;

    const int b = bh >> 4, h = bh & 15;
    const int q0 = qt*128 + row0;
    __half* yo0 = y + ((size_t)(b * CS + q0)) * CD + h*64;
    __half* yo1 = yo0 + (size_t)8 * CD;
    #pragma unroll
    for (int nd = 0; nd < 8; nd++) {
        const int col = nd*8 + 2*tg;
        __half2 h0 = __floats2half2_rn(yacc[nd][0]*inv0, yacc[nd][1]*inv0);
        __half2 h1 = __floats2half2_rn(yacc[nd][2]*inv1, yacc[nd][3]*inv1);
        *(__half2*)&yo0[col] = h0;
        *(__half2*)&yo1[col] = h1;
    }
}

// ---------------------------------------------------------------------------
extern "C" void kernel_launch(void* const* d_in, const int* in_sizes, int n_in,
                              void* d_out, int out_size)
{
    const float* x  = (const float*)d_in[0];
    const float* Wa = (const float*)d_in[1];
    const float* ba = (const float*)d_in[2];
    const float* Wp = (const float*)d_in[3];
    const float* bp = (const float*)d_in[4];
    float* out = (float*)d_out;

    __half *qkv, *y, *xh, *wa, *wp;
    cudaGetSymbolAddress((void**)&qkv, g_qkv);
    cudaGetSymbolAddress((void**)&y,   g_y);
    cudaGetSymbolAddress((void**)&xh,  g_xh);
    cudaGetSymbolAddress((void**)&wa,  g_wa);
    cudaGetSymbolAddress((void**)&wp,  g_wp);

    cudaFuncSetAttribute(gemm_h<0>,
        cudaFuncAttributeMaxDynamicSharedMemorySize, GEMM_SMEM);
    cudaFuncSetAttribute(gemm_h<1>,
        cudaFuncAttributeMaxDynamicSharedMemorySize, GEMM_SMEM);
    cudaFuncSetAttribute(attn_tc,
        cudaFuncAttributeMaxDynamicSharedMemorySize, ATTN_SMEM);

    const int ncv = N4_X + N4_WA + N4_WP;
    cvt_all_kernel<<<(ncv + 255)/256, 256>>>(x, Wa, Wp, xh, wa, wp);

    gemm_h<1><<<dim3(3*CD/128, CB*CS/128), 256, GEMM_SMEM>>>(
        xh, wa, ba, qkv, CB*CS, 3*CD, CD);
    attn_tc<<<dim3(CS/128, CBH), 256, ATTN_SMEM>>>(qkv, y);
    gemm_h<0><<<dim3(CD/128, CB*CS/128), 256, GEMM_SMEM>>>(
        y, wp, bp, out, CB*CS, CD, CD);
}